// round 4
// baseline (speedup 1.0000x reference)
#include <cuda_runtime.h>
#include <math.h>

#define NB 4
#define NCOIL 15
#define HH 320
#define WW 320
#define NF 32
#define KS 11
#define HP 342          // 320 + 2*11
#define NLUT 2048
#define LUT_MIN (-1.6f)
#define LUT_SPAN (3.2f)
#define LUT_SCALE ((float)(NLUT - 1) / LUT_SPAN)

// -------- scratch (device globals; no runtime allocation allowed) ----------
__device__ float2 g_upad[NB * HP * HP];            // ~3.7 MB
__device__ float  g_fuk[NB * NF * HP * HP];        // ~60 MB
__device__ float2 g_work[NB * NCOIL * HH * WW];    // ~49 MB
__device__ float  g_lut[NF * NLUT];
__device__ float2 g_tw[320];                       // W320^j = e^{-2pi i j/320}

// ---------------------------------------------------------------------------
__device__ __forceinline__ float2 cmulf(float2 a, float2 b) {
    return make_float2(fmaf(a.x, b.x, -(a.y * b.y)), fmaf(a.x, b.y, a.y * b.x));
}

template <int SIGN>
__device__ __forceinline__ float2 twd(const float2* tw, int idx) {
    float2 t = tw[idx];
    return make_float2(t.x, (SIGN < 0) ? t.y : -t.y);
}

// One radix-4 Stockham stage: total length 320 = n*s, n divisible by 4.
template <int SIGN, int n, int s>
__device__ __forceinline__ void stage4(const float2* __restrict__ src,
                                       float2* __restrict__ dst,
                                       const float2* tw, int t) {
    const int m = n / 4;
    const int stride = 320 / n;
    int p = t % m, q = t / m;        // m*s == 80 for all stages used
    float2 a0 = src[q + s * (p + 0 * m)];
    float2 a1 = src[q + s * (p + 1 * m)];
    float2 a2 = src[q + s * (p + 2 * m)];
    float2 a3 = src[q + s * (p + 3 * m)];
    float2 t0 = make_float2(a0.x + a2.x, a0.y + a2.y);
    float2 t1 = make_float2(a0.x - a2.x, a0.y - a2.y);
    float2 t2 = make_float2(a1.x + a3.x, a1.y + a3.y);
    float2 t3 = make_float2(a1.x - a3.x, a1.y - a3.y);
    float2 it3 = make_float2(-t3.y, t3.x);          // i * t3
    float2 A0 = make_float2(t0.x + t2.x, t0.y + t2.y);
    float2 A2 = make_float2(t0.x - t2.x, t0.y - t2.y);
    float2 A1 = make_float2(t1.x + SIGN * it3.x, t1.y + SIGN * it3.y);
    float2 A3 = make_float2(t1.x - SIGN * it3.x, t1.y - SIGN * it3.y);
    dst[q + s * (4 * p + 0)] = A0;
    dst[q + s * (4 * p + 1)] = cmulf(A1, twd<SIGN>(tw, p * stride));
    dst[q + s * (4 * p + 2)] = cmulf(A2, twd<SIGN>(tw, 2 * p * stride));
    dst[q + s * (4 * p + 3)] = cmulf(A3, twd<SIGN>(tw, 3 * p * stride));
}

// 320-point Stockham FFT (radices 5,4,4,4). X,Y: smem buffers (len 320).
// t in [0,80). Result ends up in X. Caller must have synced X before call.
template <int SIGN>
__device__ void fft320(float2* X, float2* Y, const float2* tw, int t) {
    // stage 1: n=320, r=5, m=64, s=1
    if (t < 64) {
        int p = t;
        float2 a[5];
#pragma unroll
        for (int j = 0; j < 5; j++) a[j] = X[p + 64 * j];
#pragma unroll
        for (int k = 0; k < 5; k++) {
            float2 acc = a[0];
#pragma unroll
            for (int j = 1; j < 5; j++) {
                float2 w5 = twd<SIGN>(tw, 64 * ((j * k) % 5));
                float2 pr = cmulf(a[j], w5);
                acc.x += pr.x; acc.y += pr.y;
            }
            float2 wt = twd<SIGN>(tw, p * k);   // p*k <= 252 < 320
            Y[5 * p + k] = cmulf(acc, wt);
        }
    }
    __syncthreads();
    stage4<SIGN, 64, 5>(Y, X, tw, t);
    __syncthreads();
    stage4<SIGN, 16, 20>(X, Y, tw, t);
    __syncthreads();
    stage4<SIGN, 4, 80>(Y, X, tw, t);
    __syncthreads();
    // result in X
}

// ---------------------------- init kernels ---------------------------------
__global__ void k_tw() {
    int j = threadIdx.x;
    if (j < 320) {
        double th = -2.0 * 3.14159265358979323846 * (double)j / 320.0;
        g_tw[j] = make_float2((float)cos(th), (float)sin(th));
    }
}

__global__ void k_lut(const float* __restrict__ w, const float* __restrict__ mu,
                      const float* __restrict__ sigma) {
    int f = blockIdx.x;
    float inv2s2 = 1.0f / (2.0f * sigma[0] * sigma[0]);
    for (int t = threadIdx.x; t < NLUT; t += blockDim.x) {
        float x = LUT_MIN + LUT_SPAN * (float)t / (float)(NLUT - 1);
        float acc = 0.0f;
        for (int i = 0; i < 31; i++) {
            float d = x - mu[i];
            acc += w[f * 31 + i] * expf(-d * d * inv2s2);
        }
        g_lut[f * NLUT + t] = acc;
    }
}

__global__ void k_pad(const float* __restrict__ u) {
    int idx = blockIdx.x * blockDim.x + threadIdx.x;
    if (idx >= NB * HP * HP) return;
    int x = idx % HP, y = (idx / HP) % HP, n = idx / (HP * HP);
    int sy = y - 11; sy = (sy < 0) ? -sy : ((sy > 319) ? 638 - sy : sy);
    int sx = x - 11; sx = (sx < 0) ? -sx : ((sx > 319) ? 638 - sx : sx);
    g_upad[idx] = ((const float2*)u)[(n * HH + sy) * WW + sx];
}

// --------------------- forward conv (2ch -> 32) + RBF-LUT ------------------
// tile: 32 rows x 64 cols of output, one (n,f) per block-z, 256 threads.
// Lane-contiguous x => conflict-free LDS.64; each thread: 8 output rows
// (row-sliding: each input row loaded once, reused by up to 8 rows).
// Plain scalar FFMA math.
#define CST 76   // smem row stride in float2 (74 used + 2 zero pad)
__global__ __launch_bounds__(256, 2) void k_conv(const float* __restrict__ ck) {
    __shared__ float2 sIn[42 * CST];
    __shared__ float  sLut[NLUT];
    __shared__ float4 sK4[11 * 6];   // kernel rows padded to 12 taps (6 float4)
    int nf = blockIdx.z, n = nf >> 5, f = nf & 31;
    int y0 = blockIdx.y * 32, x0 = blockIdx.x * 64;
    int tid = threadIdx.x;
    for (int i = tid; i < NLUT; i += 256) sLut[i] = g_lut[f * NLUT + i];
    const float2* ck2 = (const float2*)ck;
    if (tid < 66) {
        int ky = tid / 6, p = tid % 6;
        int kx0 = 2 * p, kx1 = 2 * p + 1;
        float2 wa = (kx0 < 11) ? ck2[f * 121 + ky * 11 + kx0] : make_float2(0.f, 0.f);
        float2 wb = (kx1 < 11) ? ck2[f * 121 + ky * 11 + kx1] : make_float2(0.f, 0.f);
        sK4[tid] = make_float4(wa.x, wa.y, wb.x, wb.y);
    }
    for (int i = tid; i < 42 * CST; i += 256) {
        int ly = i / CST, lx = i % CST;
        int gy = y0 + ly - 5, gx = x0 + lx - 5;
        float2 v = make_float2(0.f, 0.f);
        if (lx < 74 && (unsigned)gy < (unsigned)HP && (unsigned)gx < (unsigned)HP)
            v = g_upad[(n * HP + gy) * HP + gx];
        sIn[i] = v;
    }
    __syncthreads();
    int xl = tid & 63, yg = tid >> 6;   // 64 lanes in x, 4 groups of 8 rows
    float acc[8];
#pragma unroll
    for (int j = 0; j < 8; j++) acc[j] = 0.f;
#pragma unroll
    for (int r = 0; r < 18; r++) {
        float2 v[12];
#pragma unroll
        for (int kx = 0; kx < 12; kx++)
            v[kx] = sIn[(yg * 8 + r) * CST + xl + kx];
        const int jlo = (r - 10 > 0) ? (r - 10) : 0;
        const int jhi = (r < 7) ? r : 7;
#pragma unroll
        for (int j = 0; j < 8; j++) {
            if (j < jlo || j > jhi) continue;
            const int ky = r - j;
            float a = acc[j];
#pragma unroll
            for (int p = 0; p < 6; p++) {
                float4 wq = sK4[ky * 6 + p];
                a = fmaf(v[2 * p].x,     wq.x, a);
                a = fmaf(v[2 * p].y,     wq.y, a);
                a = fmaf(v[2 * p + 1].x, wq.z, a);
                a = fmaf(v[2 * p + 1].y, wq.w, a);
            }
            acc[j] = a;
        }
    }
    int x = x0 + xl;
    if (x < HP) {
#pragma unroll
        for (int j = 0; j < 8; j++) {
            int y = y0 + yg * 8 + j;
            if (y < HP) {
                float a = acc[j];
                float tpos = (a - LUT_MIN) * LUT_SCALE;
                tpos = fminf(fmaxf(tpos, 0.f), (float)(NLUT - 1) - 0.001f);
                int ii = (int)tpos;
                float fr = tpos - (float)ii;
                g_fuk[((n * NF + f) * HP + y) * HP + x] =
                    sLut[ii] + fr * (sLut[ii + 1] - sLut[ii]);
            }
        }
    }
}

// ----------------------------- FFT passes ----------------------------------
// pass 1: rows forward.  q = D*(u*cs); scale by 1/320 (full fwd ortho factor)
__global__ void k_fft_row_fwd(const float* __restrict__ u,
                              const float* __restrict__ cs) {
    __shared__ float2 sm[4][2][320];
    __shared__ float2 sTw[320];
    int tid = threadIdx.x;
    sTw[tid] = g_tw[tid];
    int g = tid / 80, t = tid % 80;
    int rowIdx = blockIdx.x * 4 + g;
    int r = rowIdx % HH, nc = rowIdx / HH;
    int n = nc / NCOIL;
    const float2* up = (const float2*)u + (n * HH + r) * WW;
    const float2* cp = (const float2*)cs + (nc * HH + r) * WW;
    float2* X = &sm[g][0][0];
    float2* Y = &sm[g][1][0];
    for (int x = t; x < 320; x += 80) {
        float2 q = cmulf(up[x], cp[x]);
        float sgn = ((r + x) & 1) ? -1.f : 1.f;
        X[x] = make_float2(sgn * q.x, sgn * q.y);
    }
    __syncthreads();
    fft320<-1>(X, Y, sTw, t);
    float2* dst = g_work + nc * (HH * WW) + r * WW;
    const float sc = 1.f / 320.f;
    for (int x = t; x < 320; x += 80)
        dst[x] = make_float2(X[x].x * sc, X[x].y * sc);
}

// pass 2: columns forward + S = m*(Q - D*f)
__global__ void k_fft_col_fwd(const float* __restrict__ fdat,
                              const float* __restrict__ mask) {
    __shared__ float2 sm[4][2][320];
    __shared__ float2 sTw[320];
    int tid = threadIdx.x;
    sTw[tid] = g_tw[tid];
    int blk = blockIdx.x;
    int nc = blk / 80, cb = (blk % 80) * 4;
    int n = nc / NCOIL;
    float2* base = g_work + nc * (HH * WW);
    for (int i = tid; i < 1280; i += 320) {
        int row = i >> 2, cc = i & 3;
        sm[cc][0][row] = base[row * WW + cb + cc];
    }
    __syncthreads();
    int g = tid / 80, t = tid % 80;
    fft320<-1>(&sm[g][0][0], &sm[g][1][0], sTw, t);
    const float2* f2 = (const float2*)fdat + nc * (HH * WW);
    for (int i = tid; i < 1280; i += 320) {
        int row = i >> 2, cc = i & 3;
        int col = cb + cc;
        float m = mask[n * (HH * WW) + row * WW + col];
        float2 fv = f2[row * WW + col];
        float sgn = ((row + col) & 1) ? -1.f : 1.f;
        float2 q = sm[cc][0][row];
        base[row * WW + col] =
            make_float2(m * (q.x - sgn * fv.x), m * (q.y - sgn * fv.y));
    }
}

// pass 3: rows inverse (conj twiddles), scale 1/320 (full inv ortho factor)
__global__ void k_fft_row_inv() {
    __shared__ float2 sm[4][2][320];
    __shared__ float2 sTw[320];
    int tid = threadIdx.x;
    sTw[tid] = g_tw[tid];
    int g = tid / 80, t = tid % 80;
    int rowIdx = blockIdx.x * 4 + g;
    int r = rowIdx % HH, nc = rowIdx / HH;
    float2* rowp = g_work + nc * (HH * WW) + r * WW;
    float2* X = &sm[g][0][0];
    float2* Y = &sm[g][1][0];
    for (int x = t; x < 320; x += 80) X[x] = rowp[x];
    __syncthreads();
    fft320<1>(X, Y, sTw, t);
    const float sc = 1.f / 320.f;
    for (int x = t; x < 320; x += 80)
        rowp[x] = make_float2(X[x].x * sc, X[x].y * sc);
}

// pass 4: columns inverse, then v -> D * v * conj(cs)  (per-coil contribution)
__global__ void k_fft_col_inv(const float* __restrict__ cs) {
    __shared__ float2 sm[4][2][320];
    __shared__ float2 sTw[320];
    int tid = threadIdx.x;
    sTw[tid] = g_tw[tid];
    int blk = blockIdx.x;
    int nc = blk / 80, cb = (blk % 80) * 4;
    float2* base = g_work + nc * (HH * WW);
    for (int i = tid; i < 1280; i += 320) {
        int row = i >> 2, cc = i & 3;
        sm[cc][0][row] = base[row * WW + cb + cc];
    }
    __syncthreads();
    int g = tid / 80, t = tid % 80;
    fft320<1>(&sm[g][0][0], &sm[g][1][0], sTw, t);
    const float2* c2 = (const float2*)cs + nc * (HH * WW);
    for (int i = tid; i < 1280; i += 320) {
        int row = i >> 2, cc = i & 3;
        int col = cb + cc;
        float2 v = sm[cc][0][row];
        float2 cv = c2[row * WW + col];
        float sgn = ((row + col) & 1) ? -1.f : 1.f;
        float2 o;
        o.x = sgn * (v.x * cv.x + v.y * cv.y);
        o.y = sgn * (v.y * cv.x - v.x * cv.y);
        base[row * WW + col] = o;
    }
}

// --------------- adjoint conv + coil sum + final combine -------------------
// tile 32 rows x 64 cols output, 256 threads, lane-contiguous x,
// 8 output rows per thread, scalar accumulators (re+im separately).
#define FST 76   // smem row stride in floats (74 used + 2 zero pad)
__global__ __launch_bounds__(256, 2) void k_final(const float* __restrict__ u,
                        const float* __restrict__ ck,
                        const float* __restrict__ lamb,
                        float2* __restrict__ out) {
    __shared__ float  sT[42 * FST];
    __shared__ float4 sK4[11 * 6];   // reversed kernel rows padded to 12 taps
    int n = blockIdx.z;
    int y0 = blockIdx.y * 32, x0 = blockIdx.x * 64;
    int tid = threadIdx.x;
    int xl = tid & 63, yg = tid >> 6;
    float ar[8], ai[8];
#pragma unroll
    for (int j = 0; j < 8; j++) { ar[j] = 0.f; ai[j] = 0.f; }
    const float2* ck2 = (const float2*)ck;
    for (int f = 0; f < NF; f++) {
        __syncthreads();
        for (int i = tid; i < 42 * FST; i += 256) {
            int ly = i / FST, lx = i % FST;
            float v = 0.f;
            if (lx < 74)
                v = g_fuk[((n * NF + f) * HP + (y0 + 6 + ly)) * HP + (x0 + 6 + lx)];
            sT[i] = v;
        }
        if (tid < 66) {
            int ky = tid / 6, p = tid % 6;
            int kx0 = 2 * p, kx1 = 2 * p + 1;
            float2 wa = (kx0 < 11) ? ck2[f * 121 + 120 - (ky * 11 + kx0)]
                                   : make_float2(0.f, 0.f);
            float2 wb = (kx1 < 11) ? ck2[f * 121 + 120 - (ky * 11 + kx1)]
                                   : make_float2(0.f, 0.f);
            sK4[tid] = make_float4(wa.x, wa.y, wb.x, wb.y);
        }
        __syncthreads();
#pragma unroll
        for (int r = 0; r < 18; r++) {
            float v[12];
#pragma unroll
            for (int kx = 0; kx < 12; kx++)
                v[kx] = sT[(yg * 8 + r) * FST + xl + kx];
            const int jlo = (r - 10 > 0) ? (r - 10) : 0;
            const int jhi = (r < 7) ? r : 7;
#pragma unroll
            for (int j = 0; j < 8; j++) {
                if (j < jlo || j > jhi) continue;
                const int ky = r - j;
                float cr = ar[j], ci = ai[j];
#pragma unroll
                for (int p = 0; p < 6; p++) {
                    float4 wq = sK4[ky * 6 + p];
                    cr = fmaf(v[2 * p],     wq.x, cr);
                    ci = fmaf(v[2 * p],     wq.y, ci);
                    cr = fmaf(v[2 * p + 1], wq.z, cr);
                    ci = fmaf(v[2 * p + 1], wq.w, ci);
                }
                ar[j] = cr; ai[j] = ci;
            }
        }
    }
    float lam = lamb[0];
    int x = x0 + xl;
#pragma unroll
    for (int j = 0; j < 8; j++) {
        int y = y0 + yg * 8 + j;
        float2 du = make_float2(0.f, 0.f);
        for (int c = 0; c < NCOIL; c++) {
            float2 vv = g_work[((n * NCOIL + c) * HH + y) * WW + x];
            du.x += vv.x; du.y += vv.y;
        }
        float2 uu = ((const float2*)u)[(n * HH + y) * WW + x];
        float2 o;
        o.x = uu.x - ar[j] * (1.f / 32.f) - lam * du.x;
        o.y = uu.y - ai[j] * (1.f / 32.f) - lam * du.y;
        out[(n * HH + y) * WW + x] = o;
    }
}

// ---------------------------------------------------------------------------
extern "C" void kernel_launch(void* const* d_in, const int* in_sizes, int n_in,
                              void* d_out, int out_size) {
    const float* u_t   = (const float*)d_in[0];
    const float* fdat  = (const float*)d_in[1];
    const float* cs    = (const float*)d_in[2];
    const float* mask  = (const float*)d_in[3];
    const float* ck    = (const float*)d_in[4];
    const float* w     = (const float*)d_in[5];
    const float* mu    = (const float*)d_in[6];
    const float* sigma = (const float*)d_in[7];
    const float* lamb  = (const float*)d_in[8];
    float2* out = (float2*)d_out;

    k_tw<<<1, 320>>>();
    k_lut<<<NF, 256>>>(w, mu, sigma);
    k_pad<<<(NB * HP * HP + 255) / 256, 256>>>(u_t);
    k_conv<<<dim3(6, 11, NB * NF), 256>>>(ck);

    int nrows = NB * NCOIL * HH;          // 19200
    k_fft_row_fwd<<<nrows / 4, 320>>>(u_t, cs);
    k_fft_col_fwd<<<NB * NCOIL * 80, 320>>>(fdat, mask);
    k_fft_row_inv<<<nrows / 4, 320>>>();
    k_fft_col_inv<<<NB * NCOIL * 80, 320>>>(cs);

    k_final<<<dim3(5, 10, NB), 256>>>(u_t, ck, lamb, out);
}

// round 9
// speedup vs baseline: 2.2746x; 2.2746x over previous
#include <cuda_runtime.h>
#include <math.h>

#define NB 4
#define NCOIL 15
#define HH 320
#define WW 320
#define NF 32
#define KS 11
#define HP 342          // 320 + 2*11
#define NLUT 2048
#define LUT_MIN (-1.6f)
#define LUT_SPAN (3.2f)
#define LUT_SCALE ((float)(NLUT - 1) / LUT_SPAN)

// -------- scratch (device globals; no runtime allocation allowed) ----------
__device__ float2 g_upad[NB * HP * HP];            // ~3.7 MB
__device__ float  g_fuk[NB * NF * HP * HP];        // ~60 MB
__device__ float2 g_work[NB * NCOIL * HH * WW];    // ~49 MB
__device__ float  g_lut[NF * NLUT];
__device__ float2 g_tw[320];                       // W320^j = e^{-2pi i j/320}

// ---------------------------------------------------------------------------
__device__ __forceinline__ float2 cmulf(float2 a, float2 b) {
    return make_float2(fmaf(a.x, b.x, -(a.y * b.y)), fmaf(a.x, b.y, a.y * b.x));
}

// ---- packed f32x2 helpers ----
__device__ __forceinline__ unsigned long long pack2(float x, float y) {
    unsigned long long r;
    asm("mov.b64 %0, {%1,%2};" : "=l"(r) : "f"(x), "f"(y));
    return r;
}
__device__ __forceinline__ void unpack2(unsigned long long v, float& x, float& y) {
    asm("mov.b64 {%0,%1}, %2;" : "=f"(x), "=f"(y) : "l"(v));
}
__device__ __forceinline__ void fma2(unsigned long long& acc,
                                     unsigned long long a, unsigned long long b) {
    asm("fma.rn.f32x2 %0, %1, %2, %0;" : "+l"(acc) : "l"(a), "l"(b));
}

template <int SIGN>
__device__ __forceinline__ float2 twd(const float2* tw, int idx) {
    float2 t = tw[idx];
    return make_float2(t.x, (SIGN < 0) ? t.y : -t.y);
}

// One radix-4 Stockham stage: total length 320 = n*s, n divisible by 4.
template <int SIGN, int n, int s>
__device__ __forceinline__ void stage4(const float2* __restrict__ src,
                                       float2* __restrict__ dst,
                                       const float2* tw, int t) {
    const int m = n / 4;
    const int stride = 320 / n;
    int p = t % m, q = t / m;        // m*s == 80 for all stages used
    float2 a0 = src[q + s * (p + 0 * m)];
    float2 a1 = src[q + s * (p + 1 * m)];
    float2 a2 = src[q + s * (p + 2 * m)];
    float2 a3 = src[q + s * (p + 3 * m)];
    float2 t0 = make_float2(a0.x + a2.x, a0.y + a2.y);
    float2 t1 = make_float2(a0.x - a2.x, a0.y - a2.y);
    float2 t2 = make_float2(a1.x + a3.x, a1.y + a3.y);
    float2 t3 = make_float2(a1.x - a3.x, a1.y - a3.y);
    float2 it3 = make_float2(-t3.y, t3.x);          // i * t3
    float2 A0 = make_float2(t0.x + t2.x, t0.y + t2.y);
    float2 A2 = make_float2(t0.x - t2.x, t0.y - t2.y);
    float2 A1 = make_float2(t1.x + SIGN * it3.x, t1.y + SIGN * it3.y);
    float2 A3 = make_float2(t1.x - SIGN * it3.x, t1.y - SIGN * it3.y);
    dst[q + s * (4 * p + 0)] = A0;
    dst[q + s * (4 * p + 1)] = cmulf(A1, twd<SIGN>(tw, p * stride));
    dst[q + s * (4 * p + 2)] = cmulf(A2, twd<SIGN>(tw, 2 * p * stride));
    dst[q + s * (4 * p + 3)] = cmulf(A3, twd<SIGN>(tw, 3 * p * stride));
}

// 320-point Stockham FFT (radices 5,4,4,4). X,Y: smem buffers (len 320).
template <int SIGN>
__device__ void fft320(float2* X, float2* Y, const float2* tw, int t) {
    if (t < 64) {
        int p = t;
        float2 a[5];
#pragma unroll
        for (int j = 0; j < 5; j++) a[j] = X[p + 64 * j];
#pragma unroll
        for (int k = 0; k < 5; k++) {
            float2 acc = a[0];
#pragma unroll
            for (int j = 1; j < 5; j++) {
                float2 w5 = twd<SIGN>(tw, 64 * ((j * k) % 5));
                float2 pr = cmulf(a[j], w5);
                acc.x += pr.x; acc.y += pr.y;
            }
            float2 wt = twd<SIGN>(tw, p * k);
            Y[5 * p + k] = cmulf(acc, wt);
        }
    }
    __syncthreads();
    stage4<SIGN, 64, 5>(Y, X, tw, t);
    __syncthreads();
    stage4<SIGN, 16, 20>(X, Y, tw, t);
    __syncthreads();
    stage4<SIGN, 4, 80>(Y, X, tw, t);
    __syncthreads();
}

// ---------------------------- init kernels ---------------------------------
__global__ void k_tw() {
    int j = threadIdx.x;
    if (j < 320) {
        double th = -2.0 * 3.14159265358979323846 * (double)j / 320.0;
        g_tw[j] = make_float2((float)cos(th), (float)sin(th));
    }
}

__global__ void k_lut(const float* __restrict__ w, const float* __restrict__ mu,
                      const float* __restrict__ sigma) {
    int f = blockIdx.x;
    float inv2s2 = 1.0f / (2.0f * sigma[0] * sigma[0]);
    for (int t = threadIdx.x; t < NLUT; t += blockDim.x) {
        float x = LUT_MIN + LUT_SPAN * (float)t / (float)(NLUT - 1);
        float acc = 0.0f;
        for (int i = 0; i < 31; i++) {
            float d = x - mu[i];
            acc += w[f * 31 + i] * expf(-d * d * inv2s2);
        }
        g_lut[f * NLUT + t] = acc;
    }
}

__global__ void k_pad(const float* __restrict__ u) {
    int idx = blockIdx.x * blockDim.x + threadIdx.x;
    if (idx >= NB * HP * HP) return;
    int x = idx % HP, y = (idx / HP) % HP, n = idx / (HP * HP);
    int sy = y - 11; sy = (sy < 0) ? -sy : ((sy > 319) ? 638 - sy : sy);
    int sx = x - 11; sx = (sx < 0) ? -sx : ((sx > 319) ? 638 - sx : sx);
    g_upad[idx] = ((const float2*)u)[(n * HH + sy) * WW + sx];
}

// --------------------- forward conv (2ch -> 32) + RBF-LUT ------------------
// tile: 32 rows x 64 cols, one (n,f) per block-z, 256 threads.
// Lanes map to ROWS (ty = tid&31): smem row stride 77 u64 (odd) =>
// conflict-free LDS.64, unprovable 16B align => no LDS.128 widening.
// Packed (re,im) in u64; weights pre-packed; 1 FFMA2 per tap per output.
#define CST 77
__global__ __launch_bounds__(256) void k_conv(const float* __restrict__ ck) {
    __shared__ unsigned long long sIn[42 * CST];   // packed (re,im)  ~25.9KB
    __shared__ float sLut[NLUT];                   // 8KB
    __shared__ unsigned long long sK[121];         // packed (wr,wi)
    int nf = blockIdx.z, n = nf >> 5, f = nf & 31;
    int y0 = blockIdx.y * 32, x0 = blockIdx.x * 64;
    int tid = threadIdx.x;
    for (int i = tid; i < NLUT; i += 256) sLut[i] = g_lut[f * NLUT + i];
    const float2* ck2 = (const float2*)ck;
    if (tid < 121) {
        float2 wv = ck2[f * 121 + tid];
        sK[tid] = pack2(wv.x, wv.y);
    }
    for (int i = tid; i < 42 * CST; i += 256) {
        int ly = i / CST, lx = i % CST;
        int gy = y0 + ly - 5, gx = x0 + lx - 5;
        float2 v = make_float2(0.f, 0.f);
        if (lx < 74 && (unsigned)gy < (unsigned)HP && (unsigned)gx < (unsigned)HP)
            v = g_upad[(n * HP + gy) * HP + gx];
        sIn[i] = pack2(v.x, v.y);
    }
    __syncthreads();
    int ty = tid & 31, txg = (tid >> 5) << 3;   // 32 rows x (8 groups * 8 cols)
    unsigned long long acc[8];
#pragma unroll
    for (int j = 0; j < 8; j++) acc[j] = 0ull;
#pragma unroll 1
    for (int ky = 0; ky < 11; ky++) {
        unsigned long long v[18];
        const unsigned long long* rowp = &sIn[(ty + ky) * CST + txg];
#pragma unroll
        for (int p = 0; p < 18; p++) v[p] = rowp[p];
#pragma unroll
        for (int kx = 0; kx < 11; kx++) {
            unsigned long long wv = sK[ky * 11 + kx];
#pragma unroll
            for (int j = 0; j < 8; j++) fma2(acc[j], v[kx + j], wv);
        }
    }
    __syncthreads();                 // sIn reads done; reuse as staging
    float* sOut = (float*)sIn;       // 32 x 65 floats
#pragma unroll
    for (int j = 0; j < 8; j++) {
        float lo, hi;
        unpack2(acc[j], lo, hi);
        float a = lo + hi;
        float tpos = (a - LUT_MIN) * LUT_SCALE;
        tpos = fminf(fmaxf(tpos, 0.f), (float)(NLUT - 1) - 0.001f);
        int ii = (int)tpos;
        float fr = tpos - (float)ii;
        sOut[ty * 65 + txg + j] = sLut[ii] + fr * (sLut[ii + 1] - sLut[ii]);
    }
    __syncthreads();
    for (int i = tid; i < 32 * 64; i += 256) {
        int row = i >> 6, col = i & 63;
        int y = y0 + row, x = x0 + col;
        if (y < HP && x < HP)
            g_fuk[((n * NF + f) * HP + y) * HP + x] = sOut[row * 65 + col];
    }
}

// ----------------------------- FFT passes ----------------------------------
__global__ void k_fft_row_fwd(const float* __restrict__ u,
                              const float* __restrict__ cs) {
    __shared__ float2 sm[4][2][320];
    __shared__ float2 sTw[320];
    int tid = threadIdx.x;
    sTw[tid] = g_tw[tid];
    int g = tid / 80, t = tid % 80;
    int rowIdx = blockIdx.x * 4 + g;
    int r = rowIdx % HH, nc = rowIdx / HH;
    int n = nc / NCOIL;
    const float2* up = (const float2*)u + (n * HH + r) * WW;
    const float2* cp = (const float2*)cs + (nc * HH + r) * WW;
    float2* X = &sm[g][0][0];
    float2* Y = &sm[g][1][0];
    for (int x = t; x < 320; x += 80) {
        float2 q = cmulf(up[x], cp[x]);
        float sgn = ((r + x) & 1) ? -1.f : 1.f;
        X[x] = make_float2(sgn * q.x, sgn * q.y);
    }
    __syncthreads();
    fft320<-1>(X, Y, sTw, t);
    float2* dst = g_work + nc * (HH * WW) + r * WW;
    const float sc = 1.f / 320.f;
    for (int x = t; x < 320; x += 80)
        dst[x] = make_float2(X[x].x * sc, X[x].y * sc);
}

__global__ void k_fft_col_fwd(const float* __restrict__ fdat,
                              const float* __restrict__ mask) {
    __shared__ float2 sm[4][2][320];
    __shared__ float2 sTw[320];
    int tid = threadIdx.x;
    sTw[tid] = g_tw[tid];
    int blk = blockIdx.x;
    int nc = blk / 80, cb = (blk % 80) * 4;
    int n = nc / NCOIL;
    float2* base = g_work + nc * (HH * WW);
    for (int i = tid; i < 1280; i += 320) {
        int row = i >> 2, cc = i & 3;
        sm[cc][0][row] = base[row * WW + cb + cc];
    }
    __syncthreads();
    int g = tid / 80, t = tid % 80;
    fft320<-1>(&sm[g][0][0], &sm[g][1][0], sTw, t);
    const float2* f2 = (const float2*)fdat + nc * (HH * WW);
    for (int i = tid; i < 1280; i += 320) {
        int row = i >> 2, cc = i & 3;
        int col = cb + cc;
        float m = mask[n * (HH * WW) + row * WW + col];
        float2 fv = f2[row * WW + col];
        float sgn = ((row + col) & 1) ? -1.f : 1.f;
        float2 q = sm[cc][0][row];
        base[row * WW + col] =
            make_float2(m * (q.x - sgn * fv.x), m * (q.y - sgn * fv.y));
    }
}

__global__ void k_fft_row_inv() {
    __shared__ float2 sm[4][2][320];
    __shared__ float2 sTw[320];
    int tid = threadIdx.x;
    sTw[tid] = g_tw[tid];
    int g = tid / 80, t = tid % 80;
    int rowIdx = blockIdx.x * 4 + g;
    int r = rowIdx % HH, nc = rowIdx / HH;
    float2* rowp = g_work + nc * (HH * WW) + r * WW;
    float2* X = &sm[g][0][0];
    float2* Y = &sm[g][1][0];
    for (int x = t; x < 320; x += 80) X[x] = rowp[x];
    __syncthreads();
    fft320<1>(X, Y, sTw, t);
    const float sc = 1.f / 320.f;
    for (int x = t; x < 320; x += 80)
        rowp[x] = make_float2(X[x].x * sc, X[x].y * sc);
}

__global__ void k_fft_col_inv(const float* __restrict__ cs) {
    __shared__ float2 sm[4][2][320];
    __shared__ float2 sTw[320];
    int tid = threadIdx.x;
    sTw[tid] = g_tw[tid];
    int blk = blockIdx.x;
    int nc = blk / 80, cb = (blk % 80) * 4;
    float2* base = g_work + nc * (HH * WW);
    for (int i = tid; i < 1280; i += 320) {
        int row = i >> 2, cc = i & 3;
        sm[cc][0][row] = base[row * WW + cb + cc];
    }
    __syncthreads();
    int g = tid / 80, t = tid % 80;
    fft320<1>(&sm[g][0][0], &sm[g][1][0], sTw, t);
    const float2* c2 = (const float2*)cs + nc * (HH * WW);
    for (int i = tid; i < 1280; i += 320) {
        int row = i >> 2, cc = i & 3;
        int col = cb + cc;
        float2 v = sm[cc][0][row];
        float2 cv = c2[row * WW + col];
        float sgn = ((row + col) & 1) ? -1.f : 1.f;
        float2 o;
        o.x = sgn * (v.x * cv.x + v.y * cv.y);
        o.y = sgn * (v.y * cv.x - v.x * cv.y);
        base[row * WW + col] = o;
    }
}

// --------------- adjoint conv + coil sum + final combine -------------------
// tile 16 rows x 64 cols, 128 threads, 400 blocks (good wave balance).
// sT holds (v,v) packed u64, stride 77 (odd) => conflict-free LDS.64.
// weights packed (wr,wi) => 1 FFMA2 per tap per output for (re,im).
#define FST 77
__global__ __launch_bounds__(128) void k_final(const float* __restrict__ u,
                        const float* __restrict__ ck,
                        const float* __restrict__ lamb,
                        float2* __restrict__ out) {
    __shared__ unsigned long long sT[26 * FST];   // 16KB
    __shared__ unsigned long long sK[121];
    int n = blockIdx.z;
    int y0 = blockIdx.y * 16, x0 = blockIdx.x * 64;
    int tid = threadIdx.x;
    int ty = tid & 15, txg = (tid >> 4) << 3;   // 16 rows x (8 groups * 8 cols)
    unsigned long long acc[8];
#pragma unroll
    for (int j = 0; j < 8; j++) acc[j] = 0ull;
    const float2* ck2 = (const float2*)ck;
#pragma unroll 1
    for (int f = 0; f < NF; f++) {
        __syncthreads();
        for (int i = tid; i < 26 * FST; i += 128) {
            int ly = i / FST, lx = i % FST;
            float v = 0.f;
            if (lx < 74)
                v = g_fuk[((n * NF + f) * HP + (y0 + 6 + ly)) * HP + (x0 + 6 + lx)];
            sT[i] = pack2(v, v);
        }
        if (tid < 121) {
            float2 wv = ck2[f * 121 + 120 - tid];   // reversed kernel
            sK[tid] = pack2(wv.x, wv.y);
        }
        __syncthreads();
#pragma unroll 1
        for (int ky = 0; ky < 11; ky++) {
            unsigned long long v[18];
            const unsigned long long* rowp = &sT[(ty + ky) * FST + txg];
#pragma unroll
            for (int p = 0; p < 18; p++) v[p] = rowp[p];
#pragma unroll
            for (int kx = 0; kx < 11; kx++) {
                unsigned long long wv = sK[ky * 11 + kx];
#pragma unroll
                for (int j = 0; j < 8; j++) fma2(acc[j], v[kx + j], wv);
            }
        }
    }
    __syncthreads();
    float2* sOut = (float2*)sT;   // 16 x 65 float2
#pragma unroll
    for (int j = 0; j < 8; j++) {
        float ar, ai;
        unpack2(acc[j], ar, ai);
        sOut[ty * 65 + txg + j] = make_float2(ar, ai);
    }
    __syncthreads();
    float lam = lamb[0];
    for (int i = tid; i < 16 * 64; i += 128) {
        int row = i >> 6, col = i & 63;
        int y = y0 + row, x = x0 + col;
        float2 du = make_float2(0.f, 0.f);
#pragma unroll 1
        for (int c = 0; c < NCOIL; c++) {
            float2 vv = g_work[((n * NCOIL + c) * HH + y) * WW + x];
            du.x += vv.x; du.y += vv.y;
        }
        float2 uu = ((const float2*)u)[(n * HH + y) * WW + x];
        float2 r = sOut[row * 65 + col];
        float2 o;
        o.x = uu.x - r.x * (1.f / 32.f) - lam * du.x;
        o.y = uu.y - r.y * (1.f / 32.f) - lam * du.y;
        out[(n * HH + y) * WW + x] = o;
    }
}

// ---------------------------------------------------------------------------
extern "C" void kernel_launch(void* const* d_in, const int* in_sizes, int n_in,
                              void* d_out, int out_size) {
    const float* u_t   = (const float*)d_in[0];
    const float* fdat  = (const float*)d_in[1];
    const float* cs    = (const float*)d_in[2];
    const float* mask  = (const float*)d_in[3];
    const float* ck    = (const float*)d_in[4];
    const float* w     = (const float*)d_in[5];
    const float* mu    = (const float*)d_in[6];
    const float* sigma = (const float*)d_in[7];
    const float* lamb  = (const float*)d_in[8];
    float2* out = (float2*)d_out;

    k_tw<<<1, 320>>>();
    k_lut<<<NF, 256>>>(w, mu, sigma);
    k_pad<<<(NB * HP * HP + 255) / 256, 256>>>(u_t);
    k_conv<<<dim3(6, 11, NB * NF), 256>>>(ck);

    int nrows = NB * NCOIL * HH;          // 19200
    k_fft_row_fwd<<<nrows / 4, 320>>>(u_t, cs);
    k_fft_col_fwd<<<NB * NCOIL * 80, 320>>>(fdat, mask);
    k_fft_row_inv<<<nrows / 4, 320>>>();
    k_fft_col_inv<<<NB * NCOIL * 80, 320>>>(cs);

    k_final<<<dim3(5, 20, NB), 128>>>(u_t, ck, lamb, out);
}

// round 10
// speedup vs baseline: 2.5312x; 1.1128x over previous
#include <cuda_runtime.h>
#include <math.h>

#define NB 4
#define NCOIL 15
#define HH 320
#define WW 320
#define NF 32
#define KS 11
#define HP 342          // 320 + 2*11
#define NLUT 2048
#define LUT_MIN (-1.6f)
#define LUT_SPAN (3.2f)
#define LUT_SCALE ((float)(NLUT - 1) / LUT_SPAN)

// -------- scratch (device globals; no runtime allocation allowed) ----------
__device__ float2 g_upad[NB * HP * HP];            // ~3.7 MB
__device__ float  g_fuk[NB * NF * HP * HP];        // ~60 MB
__device__ float2 g_work[NB * NCOIL * HH * WW];    // ~49 MB
__device__ float2 g_adj[4 * NB * HH * WW];         // 13.1 MB adjoint partials
__device__ float  g_lut[NF * NLUT];
__device__ float2 g_tw[320];                       // W320^j = e^{-2pi i j/320}

// ---------------------------------------------------------------------------
__device__ __forceinline__ float2 cmulf(float2 a, float2 b) {
    return make_float2(fmaf(a.x, b.x, -(a.y * b.y)), fmaf(a.x, b.y, a.y * b.x));
}

// ---- packed f32x2 helpers ----
__device__ __forceinline__ unsigned long long pack2(float x, float y) {
    unsigned long long r;
    asm("mov.b64 %0, {%1,%2};" : "=l"(r) : "f"(x), "f"(y));
    return r;
}
__device__ __forceinline__ void unpack2(unsigned long long v, float& x, float& y) {
    asm("mov.b64 {%0,%1}, %2;" : "=f"(x), "=f"(y) : "l"(v));
}
__device__ __forceinline__ void fma2(unsigned long long& acc,
                                     unsigned long long a, unsigned long long b) {
    asm("fma.rn.f32x2 %0, %1, %2, %0;" : "+l"(acc) : "l"(a), "l"(b));
}

template <int SIGN>
__device__ __forceinline__ float2 twd(const float2* tw, int idx) {
    float2 t = tw[idx];
    return make_float2(t.x, (SIGN < 0) ? t.y : -t.y);
}

// One radix-4 Stockham stage: total length 320 = n*s, n divisible by 4.
template <int SIGN, int n, int s>
__device__ __forceinline__ void stage4(const float2* __restrict__ src,
                                       float2* __restrict__ dst,
                                       const float2* tw, int t) {
    const int m = n / 4;
    const int stride = 320 / n;
    int p = t % m, q = t / m;        // m*s == 80 for all stages used
    float2 a0 = src[q + s * (p + 0 * m)];
    float2 a1 = src[q + s * (p + 1 * m)];
    float2 a2 = src[q + s * (p + 2 * m)];
    float2 a3 = src[q + s * (p + 3 * m)];
    float2 t0 = make_float2(a0.x + a2.x, a0.y + a2.y);
    float2 t1 = make_float2(a0.x - a2.x, a0.y - a2.y);
    float2 t2 = make_float2(a1.x + a3.x, a1.y + a3.y);
    float2 t3 = make_float2(a1.x - a3.x, a1.y - a3.y);
    float2 it3 = make_float2(-t3.y, t3.x);          // i * t3
    float2 A0 = make_float2(t0.x + t2.x, t0.y + t2.y);
    float2 A2 = make_float2(t0.x - t2.x, t0.y - t2.y);
    float2 A1 = make_float2(t1.x + SIGN * it3.x, t1.y + SIGN * it3.y);
    float2 A3 = make_float2(t1.x - SIGN * it3.x, t1.y - SIGN * it3.y);
    dst[q + s * (4 * p + 0)] = A0;
    dst[q + s * (4 * p + 1)] = cmulf(A1, twd<SIGN>(tw, p * stride));
    dst[q + s * (4 * p + 2)] = cmulf(A2, twd<SIGN>(tw, 2 * p * stride));
    dst[q + s * (4 * p + 3)] = cmulf(A3, twd<SIGN>(tw, 3 * p * stride));
}

// 320-point Stockham FFT (radices 5,4,4,4). X,Y: smem buffers (len 320).
template <int SIGN>
__device__ void fft320(float2* X, float2* Y, const float2* tw, int t) {
    if (t < 64) {
        int p = t;
        float2 a[5];
#pragma unroll
        for (int j = 0; j < 5; j++) a[j] = X[p + 64 * j];
#pragma unroll
        for (int k = 0; k < 5; k++) {
            float2 acc = a[0];
#pragma unroll
            for (int j = 1; j < 5; j++) {
                float2 w5 = twd<SIGN>(tw, 64 * ((j * k) % 5));
                float2 pr = cmulf(a[j], w5);
                acc.x += pr.x; acc.y += pr.y;
            }
            float2 wt = twd<SIGN>(tw, p * k);
            Y[5 * p + k] = cmulf(acc, wt);
        }
    }
    __syncthreads();
    stage4<SIGN, 64, 5>(Y, X, tw, t);
    __syncthreads();
    stage4<SIGN, 16, 20>(X, Y, tw, t);
    __syncthreads();
    stage4<SIGN, 4, 80>(Y, X, tw, t);
    __syncthreads();
}

// ---------------------------- init kernels ---------------------------------
__global__ void k_tw() {
    int j = threadIdx.x;
    if (j < 320) {
        double th = -2.0 * 3.14159265358979323846 * (double)j / 320.0;
        g_tw[j] = make_float2((float)cos(th), (float)sin(th));
    }
}

__global__ void k_lut(const float* __restrict__ w, const float* __restrict__ mu,
                      const float* __restrict__ sigma) {
    int f = blockIdx.x;
    float inv2s2 = 1.0f / (2.0f * sigma[0] * sigma[0]);
    for (int t = threadIdx.x; t < NLUT; t += blockDim.x) {
        float x = LUT_MIN + LUT_SPAN * (float)t / (float)(NLUT - 1);
        float acc = 0.0f;
        for (int i = 0; i < 31; i++) {
            float d = x - mu[i];
            acc += w[f * 31 + i] * expf(-d * d * inv2s2);
        }
        g_lut[f * NLUT + t] = acc;
    }
}

__global__ void k_pad(const float* __restrict__ u) {
    int idx = blockIdx.x * blockDim.x + threadIdx.x;
    if (idx >= NB * HP * HP) return;
    int x = idx % HP, y = (idx / HP) % HP, n = idx / (HP * HP);
    int sy = y - 11; sy = (sy < 0) ? -sy : ((sy > 319) ? 638 - sy : sy);
    int sx = x - 11; sx = (sx < 0) ? -sx : ((sx > 319) ? 638 - sx : sx);
    g_upad[idx] = ((const float2*)u)[(n * HH + sy) * WW + sx];
}

// --------------------- forward conv (2ch -> 32) + RBF-LUT ------------------
// (unchanged from R4 — proven: 205us, regs=36, occ 72%)
#define CST 77
__global__ __launch_bounds__(256) void k_conv(const float* __restrict__ ck) {
    __shared__ unsigned long long sIn[42 * CST];   // packed (re,im)  ~25.9KB
    __shared__ float sLut[NLUT];                   // 8KB
    __shared__ unsigned long long sK[121];         // packed (wr,wi)
    int nf = blockIdx.z, n = nf >> 5, f = nf & 31;
    int y0 = blockIdx.y * 32, x0 = blockIdx.x * 64;
    int tid = threadIdx.x;
    for (int i = tid; i < NLUT; i += 256) sLut[i] = g_lut[f * NLUT + i];
    const float2* ck2 = (const float2*)ck;
    if (tid < 121) {
        float2 wv = ck2[f * 121 + tid];
        sK[tid] = pack2(wv.x, wv.y);
    }
    for (int i = tid; i < 42 * CST; i += 256) {
        int ly = i / CST, lx = i % CST;
        int gy = y0 + ly - 5, gx = x0 + lx - 5;
        float2 v = make_float2(0.f, 0.f);
        if (lx < 74 && (unsigned)gy < (unsigned)HP && (unsigned)gx < (unsigned)HP)
            v = g_upad[(n * HP + gy) * HP + gx];
        sIn[i] = pack2(v.x, v.y);
    }
    __syncthreads();
    int ty = tid & 31, txg = (tid >> 5) << 3;   // 32 rows x (8 groups * 8 cols)
    unsigned long long acc[8];
#pragma unroll
    for (int j = 0; j < 8; j++) acc[j] = 0ull;
#pragma unroll 1
    for (int ky = 0; ky < 11; ky++) {
        unsigned long long v[18];
        const unsigned long long* rowp = &sIn[(ty + ky) * CST + txg];
#pragma unroll
        for (int p = 0; p < 18; p++) v[p] = rowp[p];
#pragma unroll
        for (int kx = 0; kx < 11; kx++) {
            unsigned long long wv = sK[ky * 11 + kx];
#pragma unroll
            for (int j = 0; j < 8; j++) fma2(acc[j], v[kx + j], wv);
        }
    }
    __syncthreads();                 // sIn reads done; reuse as staging
    float* sOut = (float*)sIn;       // 32 x 65 floats
#pragma unroll
    for (int j = 0; j < 8; j++) {
        float lo, hi;
        unpack2(acc[j], lo, hi);
        float a = lo + hi;
        float tpos = (a - LUT_MIN) * LUT_SCALE;
        tpos = fminf(fmaxf(tpos, 0.f), (float)(NLUT - 1) - 0.001f);
        int ii = (int)tpos;
        float fr = tpos - (float)ii;
        sOut[ty * 65 + txg + j] = sLut[ii] + fr * (sLut[ii + 1] - sLut[ii]);
    }
    __syncthreads();
    for (int i = tid; i < 32 * 64; i += 256) {
        int row = i >> 6, col = i & 63;
        int y = y0 + row, x = x0 + col;
        if (y < HP && x < HP)
            g_fuk[((n * NF + f) * HP + y) * HP + x] = sOut[row * 65 + col];
    }
}

// ----------------------------- FFT passes (unchanged) ----------------------
__global__ void k_fft_row_fwd(const float* __restrict__ u,
                              const float* __restrict__ cs) {
    __shared__ float2 sm[4][2][320];
    __shared__ float2 sTw[320];
    int tid = threadIdx.x;
    sTw[tid] = g_tw[tid];
    int g = tid / 80, t = tid % 80;
    int rowIdx = blockIdx.x * 4 + g;
    int r = rowIdx % HH, nc = rowIdx / HH;
    int n = nc / NCOIL;
    const float2* up = (const float2*)u + (n * HH + r) * WW;
    const float2* cp = (const float2*)cs + (nc * HH + r) * WW;
    float2* X = &sm[g][0][0];
    float2* Y = &sm[g][1][0];
    for (int x = t; x < 320; x += 80) {
        float2 q = cmulf(up[x], cp[x]);
        float sgn = ((r + x) & 1) ? -1.f : 1.f;
        X[x] = make_float2(sgn * q.x, sgn * q.y);
    }
    __syncthreads();
    fft320<-1>(X, Y, sTw, t);
    float2* dst = g_work + nc * (HH * WW) + r * WW;
    const float sc = 1.f / 320.f;
    for (int x = t; x < 320; x += 80)
        dst[x] = make_float2(X[x].x * sc, X[x].y * sc);
}

__global__ void k_fft_col_fwd(const float* __restrict__ fdat,
                              const float* __restrict__ mask) {
    __shared__ float2 sm[4][2][320];
    __shared__ float2 sTw[320];
    int tid = threadIdx.x;
    sTw[tid] = g_tw[tid];
    int blk = blockIdx.x;
    int nc = blk / 80, cb = (blk % 80) * 4;
    int n = nc / NCOIL;
    float2* base = g_work + nc * (HH * WW);
    for (int i = tid; i < 1280; i += 320) {
        int row = i >> 2, cc = i & 3;
        sm[cc][0][row] = base[row * WW + cb + cc];
    }
    __syncthreads();
    int g = tid / 80, t = tid % 80;
    fft320<-1>(&sm[g][0][0], &sm[g][1][0], sTw, t);
    const float2* f2 = (const float2*)fdat + nc * (HH * WW);
    for (int i = tid; i < 1280; i += 320) {
        int row = i >> 2, cc = i & 3;
        int col = cb + cc;
        float m = mask[n * (HH * WW) + row * WW + col];
        float2 fv = f2[row * WW + col];
        float sgn = ((row + col) & 1) ? -1.f : 1.f;
        float2 q = sm[cc][0][row];
        base[row * WW + col] =
            make_float2(m * (q.x - sgn * fv.x), m * (q.y - sgn * fv.y));
    }
}

__global__ void k_fft_row_inv() {
    __shared__ float2 sm[4][2][320];
    __shared__ float2 sTw[320];
    int tid = threadIdx.x;
    sTw[tid] = g_tw[tid];
    int g = tid / 80, t = tid % 80;
    int rowIdx = blockIdx.x * 4 + g;
    int r = rowIdx % HH, nc = rowIdx / HH;
    float2* rowp = g_work + nc * (HH * WW) + r * WW;
    float2* X = &sm[g][0][0];
    float2* Y = &sm[g][1][0];
    for (int x = t; x < 320; x += 80) X[x] = rowp[x];
    __syncthreads();
    fft320<1>(X, Y, sTw, t);
    const float sc = 1.f / 320.f;
    for (int x = t; x < 320; x += 80)
        rowp[x] = make_float2(X[x].x * sc, X[x].y * sc);
}

__global__ void k_fft_col_inv(const float* __restrict__ cs) {
    __shared__ float2 sm[4][2][320];
    __shared__ float2 sTw[320];
    int tid = threadIdx.x;
    sTw[tid] = g_tw[tid];
    int blk = blockIdx.x;
    int nc = blk / 80, cb = (blk % 80) * 4;
    float2* base = g_work + nc * (HH * WW);
    for (int i = tid; i < 1280; i += 320) {
        int row = i >> 2, cc = i & 3;
        sm[cc][0][row] = base[row * WW + cb + cc];
    }
    __syncthreads();
    int g = tid / 80, t = tid % 80;
    fft320<1>(&sm[g][0][0], &sm[g][1][0], sTw, t);
    const float2* c2 = (const float2*)cs + nc * (HH * WW);
    for (int i = tid; i < 1280; i += 320) {
        int row = i >> 2, cc = i & 3;
        int col = cb + cc;
        float2 v = sm[cc][0][row];
        float2 cv = c2[row * WW + col];
        float sgn = ((row + col) & 1) ? -1.f : 1.f;
        float2 o;
        o.x = sgn * (v.x * cv.x + v.y * cv.y);
        o.y = sgn * (v.y * cv.x - v.x * cv.y);
        base[row * WW + col] = o;
    }
}

// ----------------- adjoint conv partials (feature-paired) ------------------
// grid (5, 20, NB*4): tile 16 rows x 64 cols, chunk = 4 feature-PAIRS
// (8 features). sT packs two features' values per u64; weights packed
// (wreA,wreB) / (wimA,wimB); separate re/im accumulator banks.
// Inner input LDS halves vs non-paired; 1600 blocks for latency hiding.
#define FST 77
__global__ __launch_bounds__(128) void k_adj(const float* __restrict__ ck) {
    __shared__ unsigned long long sT[26 * FST];      // 16KB
    __shared__ unsigned long long sKre[121], sKim[121];
    int zz = blockIdx.z, n = zz >> 2, chunk = zz & 3;
    int y0 = blockIdx.y * 16, x0 = blockIdx.x * 64;
    int tid = threadIdx.x;
    int ty = tid & 15, txg = (tid >> 4) << 3;   // 16 rows x (8 groups * 8 cols)
    unsigned long long accre[8], accim[8];
#pragma unroll
    for (int j = 0; j < 8; j++) { accre[j] = 0ull; accim[j] = 0ull; }
    const float2* ck2 = (const float2*)ck;
#pragma unroll 1
    for (int p = 0; p < 4; p++) {
        int fA = (chunk * 4 + p) * 2, fB = fA + 1;
        __syncthreads();
        const float* baseA = &g_fuk[(n * NF + fA) * HP * HP];
        const float* baseB = &g_fuk[(n * NF + fB) * HP * HP];
        for (int i = tid; i < 26 * FST; i += 128) {
            int ly = i / FST, lx = i % FST;
            float vA = 0.f, vB = 0.f;
            if (lx < 74) {
                int off = (y0 + 6 + ly) * HP + (x0 + 6 + lx);
                vA = baseA[off];
                vB = baseB[off];
            }
            sT[i] = pack2(vA, vB);
        }
        if (tid < 121) {
            float2 wA = ck2[fA * 121 + 120 - tid];   // reversed kernel
            float2 wB = ck2[fB * 121 + 120 - tid];
            sKre[tid] = pack2(wA.x, wB.x);
            sKim[tid] = pack2(wA.y, wB.y);
        }
        __syncthreads();
#pragma unroll 1
        for (int ky = 0; ky < 11; ky++) {
            unsigned long long v[18];
            const unsigned long long* rowp = &sT[(ty + ky) * FST + txg];
#pragma unroll
            for (int q = 0; q < 18; q++) v[q] = rowp[q];
#pragma unroll
            for (int kx = 0; kx < 11; kx++) {
                unsigned long long wre = sKre[ky * 11 + kx];
                unsigned long long wim = sKim[ky * 11 + kx];
#pragma unroll
                for (int j = 0; j < 8; j++) {
                    fma2(accre[j], v[kx + j], wre);
                    fma2(accim[j], v[kx + j], wim);
                }
            }
        }
    }
    int y = y0 + ty;
    float2* dst = &g_adj[((chunk * NB + n) * HH + y) * WW + x0 + txg];
#pragma unroll
    for (int j = 0; j < 8; j++) {
        float a, b, c, d;
        unpack2(accre[j], a, b);
        unpack2(accim[j], c, d);
        dst[j] = make_float2(a + b, c + d);
    }
}

// ------------- final combine: u - Ru - Du  (memory-light) ------------------
__global__ void k_combine(const float* __restrict__ u,
                          const float* __restrict__ lamb,
                          float2* __restrict__ out) {
    int idx = blockIdx.x * blockDim.x + threadIdx.x;
    if (idx >= NB * HH * WW) return;
    int pix = idx % (HH * WW), n = idx / (HH * WW);
    float lam = lamb[0];
    float2 ru = make_float2(0.f, 0.f);
#pragma unroll
    for (int c = 0; c < 4; c++) {
        float2 v = g_adj[(c * NB + n) * (HH * WW) + pix];
        ru.x += v.x; ru.y += v.y;
    }
    float2 du = make_float2(0.f, 0.f);
#pragma unroll 1
    for (int c = 0; c < NCOIL; c++) {
        float2 v = g_work[(n * NCOIL + c) * (HH * WW) + pix];
        du.x += v.x; du.y += v.y;
    }
    float2 uu = ((const float2*)u)[idx];
    float2 o;
    o.x = uu.x - ru.x * (1.f / 32.f) - lam * du.x;
    o.y = uu.y - ru.y * (1.f / 32.f) - lam * du.y;
    out[idx] = o;
}

// ---------------------------------------------------------------------------
extern "C" void kernel_launch(void* const* d_in, const int* in_sizes, int n_in,
                              void* d_out, int out_size) {
    const float* u_t   = (const float*)d_in[0];
    const float* fdat  = (const float*)d_in[1];
    const float* cs    = (const float*)d_in[2];
    const float* mask  = (const float*)d_in[3];
    const float* ck    = (const float*)d_in[4];
    const float* w     = (const float*)d_in[5];
    const float* mu    = (const float*)d_in[6];
    const float* sigma = (const float*)d_in[7];
    const float* lamb  = (const float*)d_in[8];
    float2* out = (float2*)d_out;

    k_tw<<<1, 320>>>();
    k_lut<<<NF, 256>>>(w, mu, sigma);
    k_pad<<<(NB * HP * HP + 255) / 256, 256>>>(u_t);
    k_conv<<<dim3(6, 11, NB * NF), 256>>>(ck);

    int nrows = NB * NCOIL * HH;          // 19200
    k_fft_row_fwd<<<nrows / 4, 320>>>(u_t, cs);
    k_fft_col_fwd<<<NB * NCOIL * 80, 320>>>(fdat, mask);
    k_fft_row_inv<<<nrows / 4, 320>>>();
    k_fft_col_inv<<<NB * NCOIL * 80, 320>>>(cs);

    k_adj<<<dim3(5, 20, NB * 4), 128>>>(ck);
    k_combine<<<(NB * HH * WW + 255) / 256, 256>>>(u_t, lamb, out);
}

// round 11
// speedup vs baseline: 2.5954x; 1.0253x over previous
#include <cuda_runtime.h>
#include <math.h>

#define NB 4
#define NCOIL 15
#define HH 320
#define WW 320
#define NF 32
#define KS 11
#define HP 342          // 320 + 2*11
#define NLUT 2048
#define LUT_MIN (-1.6f)
#define LUT_SPAN (3.2f)
#define LUT_SCALE ((float)(NLUT - 1) / LUT_SPAN)

// -------- scratch (device globals; no runtime allocation allowed) ----------
__device__ float2 g_upad[NB * HP * HP];            // ~3.7 MB
__device__ float  g_fuk[NB * NF * HP * HP];        // ~60 MB
__device__ float2 g_work[NB * NCOIL * HH * WW];    // ~49 MB
__device__ float2 g_adj[4 * NB * HH * WW];         // 13.1 MB adjoint partials
__device__ float  g_lut[NF * NLUT];
__device__ float2 g_tw[320];                       // W320^j = e^{-2pi i j/320}

// ---------------------------------------------------------------------------
__device__ __forceinline__ float2 cmulf(float2 a, float2 b) {
    return make_float2(fmaf(a.x, b.x, -(a.y * b.y)), fmaf(a.x, b.y, a.y * b.x));
}

// ---- packed f32x2 helpers ----
__device__ __forceinline__ unsigned long long pack2(float x, float y) {
    unsigned long long r;
    asm("mov.b64 %0, {%1,%2};" : "=l"(r) : "f"(x), "f"(y));
    return r;
}
__device__ __forceinline__ void unpack2(unsigned long long v, float& x, float& y) {
    asm("mov.b64 {%0,%1}, %2;" : "=f"(x), "=f"(y) : "l"(v));
}
__device__ __forceinline__ void fma2(unsigned long long& acc,
                                     unsigned long long a, unsigned long long b) {
    asm("fma.rn.f32x2 %0, %1, %2, %0;" : "+l"(acc) : "l"(a), "l"(b));
}

template <int SIGN>
__device__ __forceinline__ float2 twd(const float2* tw, int idx) {
    float2 t = tw[idx];
    return make_float2(t.x, (SIGN < 0) ? t.y : -t.y);
}

// One radix-4 Stockham stage: total length 320 = n*s, n divisible by 4.
template <int SIGN, int n, int s>
__device__ __forceinline__ void stage4(const float2* __restrict__ src,
                                       float2* __restrict__ dst,
                                       const float2* tw, int t) {
    const int m = n / 4;
    const int stride = 320 / n;
    int p = t % m, q = t / m;        // m*s == 80 for all stages used
    float2 a0 = src[q + s * (p + 0 * m)];
    float2 a1 = src[q + s * (p + 1 * m)];
    float2 a2 = src[q + s * (p + 2 * m)];
    float2 a3 = src[q + s * (p + 3 * m)];
    float2 t0 = make_float2(a0.x + a2.x, a0.y + a2.y);
    float2 t1 = make_float2(a0.x - a2.x, a0.y - a2.y);
    float2 t2 = make_float2(a1.x + a3.x, a1.y + a3.y);
    float2 t3 = make_float2(a1.x - a3.x, a1.y - a3.y);
    float2 it3 = make_float2(-t3.y, t3.x);          // i * t3
    float2 A0 = make_float2(t0.x + t2.x, t0.y + t2.y);
    float2 A2 = make_float2(t0.x - t2.x, t0.y - t2.y);
    float2 A1 = make_float2(t1.x + SIGN * it3.x, t1.y + SIGN * it3.y);
    float2 A3 = make_float2(t1.x - SIGN * it3.x, t1.y - SIGN * it3.y);
    dst[q + s * (4 * p + 0)] = A0;
    dst[q + s * (4 * p + 1)] = cmulf(A1, twd<SIGN>(tw, p * stride));
    dst[q + s * (4 * p + 2)] = cmulf(A2, twd<SIGN>(tw, 2 * p * stride));
    dst[q + s * (4 * p + 3)] = cmulf(A3, twd<SIGN>(tw, 3 * p * stride));
}

// 320-point Stockham FFT (radices 5,4,4,4). X,Y: smem buffers (len 320).
template <int SIGN>
__device__ void fft320(float2* X, float2* Y, const float2* tw, int t) {
    if (t < 64) {
        int p = t;
        float2 a[5];
#pragma unroll
        for (int j = 0; j < 5; j++) a[j] = X[p + 64 * j];
#pragma unroll
        for (int k = 0; k < 5; k++) {
            float2 acc = a[0];
#pragma unroll
            for (int j = 1; j < 5; j++) {
                float2 w5 = twd<SIGN>(tw, 64 * ((j * k) % 5));
                float2 pr = cmulf(a[j], w5);
                acc.x += pr.x; acc.y += pr.y;
            }
            float2 wt = twd<SIGN>(tw, p * k);
            Y[5 * p + k] = cmulf(acc, wt);
        }
    }
    __syncthreads();
    stage4<SIGN, 64, 5>(Y, X, tw, t);
    __syncthreads();
    stage4<SIGN, 16, 20>(X, Y, tw, t);
    __syncthreads();
    stage4<SIGN, 4, 80>(Y, X, tw, t);
    __syncthreads();
}

// ---------------------------- init kernels ---------------------------------
__global__ void k_tw() {
    int j = threadIdx.x;
    if (j < 320) {
        double th = -2.0 * 3.14159265358979323846 * (double)j / 320.0;
        g_tw[j] = make_float2((float)cos(th), (float)sin(th));
    }
}

__global__ void k_lut(const float* __restrict__ w, const float* __restrict__ mu,
                      const float* __restrict__ sigma) {
    int f = blockIdx.x;
    float inv2s2 = 1.0f / (2.0f * sigma[0] * sigma[0]);
    for (int t = threadIdx.x; t < NLUT; t += blockDim.x) {
        float x = LUT_MIN + LUT_SPAN * (float)t / (float)(NLUT - 1);
        float acc = 0.0f;
        for (int i = 0; i < 31; i++) {
            float d = x - mu[i];
            acc += w[f * 31 + i] * expf(-d * d * inv2s2);
        }
        g_lut[f * NLUT + t] = acc;
    }
}

__global__ void k_pad(const float* __restrict__ u) {
    int idx = blockIdx.x * blockDim.x + threadIdx.x;
    if (idx >= NB * HP * HP) return;
    int x = idx % HP, y = (idx / HP) % HP, n = idx / (HP * HP);
    int sy = y - 11; sy = (sy < 0) ? -sy : ((sy > 319) ? 638 - sy : sy);
    int sx = x - 11; sx = (sx < 0) ? -sx : ((sx > 319) ? 638 - sx : sx);
    g_upad[idx] = ((const float2*)u)[(n * HH + sy) * WW + sx];
}

// ------------- forward conv (2ch -> 32, 2 features/block) + RBF-LUT --------
// tile: 32 rows x 64 cols, blockIdx.z = (n, feature-pair), 256 threads.
// sIn shared by both features; weights as ulonglong2 -> one LDS.128;
// two accumulator banks. LDS:FMA halves vs one-feature version.
#define CST 77
__global__ __launch_bounds__(256) void k_conv(const float* __restrict__ ck) {
    __shared__ unsigned long long sIn[42 * CST];   // packed (re,im)  ~25.9KB
    __shared__ float sLut[2][NLUT];                // 16KB
    __shared__ ulonglong2 sK[121];                 // {wA(re,im), wB(re,im)}
    int nf2 = blockIdx.z, n = nf2 >> 4, fp = nf2 & 15;
    int fA = fp * 2, fB = fA + 1;
    int y0 = blockIdx.y * 32, x0 = blockIdx.x * 64;
    int tid = threadIdx.x;
    for (int i = tid; i < NLUT; i += 256) {
        sLut[0][i] = g_lut[fA * NLUT + i];
        sLut[1][i] = g_lut[fB * NLUT + i];
    }
    const float2* ck2 = (const float2*)ck;
    if (tid < 121) {
        float2 wa = ck2[fA * 121 + tid];
        float2 wb = ck2[fB * 121 + tid];
        sK[tid] = make_ulonglong2(pack2(wa.x, wa.y), pack2(wb.x, wb.y));
    }
    for (int i = tid; i < 42 * CST; i += 256) {
        int ly = i / CST, lx = i % CST;
        int gy = y0 + ly - 5, gx = x0 + lx - 5;
        float2 v = make_float2(0.f, 0.f);
        if (lx < 74 && (unsigned)gy < (unsigned)HP && (unsigned)gx < (unsigned)HP)
            v = g_upad[(n * HP + gy) * HP + gx];
        sIn[i] = pack2(v.x, v.y);
    }
    __syncthreads();
    int ty = tid & 31, txg = (tid >> 5) << 3;   // 32 rows x (8 groups * 8 cols)
    unsigned long long accA[8], accB[8];
#pragma unroll
    for (int j = 0; j < 8; j++) { accA[j] = 0ull; accB[j] = 0ull; }
#pragma unroll 1
    for (int ky = 0; ky < 11; ky++) {
        unsigned long long v[18];
        const unsigned long long* rowp = &sIn[(ty + ky) * CST + txg];
#pragma unroll
        for (int p = 0; p < 18; p++) v[p] = rowp[p];
#pragma unroll
        for (int kx = 0; kx < 11; kx++) {
            ulonglong2 wv = sK[ky * 11 + kx];
#pragma unroll
            for (int j = 0; j < 8; j++) {
                fma2(accA[j], v[kx + j], wv.x);
                fma2(accB[j], v[kx + j], wv.y);
            }
        }
    }
    __syncthreads();                 // sIn reads done; reuse as staging
    float* sOut = (float*)sIn;       // 2 planes of 32 x 65 floats
#pragma unroll
    for (int j = 0; j < 8; j++) {
        float lo, hi;
        unpack2(accA[j], lo, hi);
        float a = lo + hi;
        float tpos = (a - LUT_MIN) * LUT_SCALE;
        tpos = fminf(fmaxf(tpos, 0.f), (float)(NLUT - 1) - 0.001f);
        int ii = (int)tpos;
        float fr = tpos - (float)ii;
        sOut[ty * 65 + txg + j] = sLut[0][ii] + fr * (sLut[0][ii + 1] - sLut[0][ii]);
        unpack2(accB[j], lo, hi);
        a = lo + hi;
        tpos = (a - LUT_MIN) * LUT_SCALE;
        tpos = fminf(fmaxf(tpos, 0.f), (float)(NLUT - 1) - 0.001f);
        ii = (int)tpos;
        fr = tpos - (float)ii;
        sOut[2080 + ty * 65 + txg + j] = sLut[1][ii] + fr * (sLut[1][ii + 1] - sLut[1][ii]);
    }
    __syncthreads();
    for (int i = tid; i < 32 * 64; i += 256) {
        int row = i >> 6, col = i & 63;
        int y = y0 + row, x = x0 + col;
        if (y < HP && x < HP) {
            g_fuk[((n * NF + fA) * HP + y) * HP + x] = sOut[row * 65 + col];
            g_fuk[((n * NF + fB) * HP + y) * HP + x] = sOut[2080 + row * 65 + col];
        }
    }
}

// ----------------------------- FFT passes (unchanged) ----------------------
__global__ void k_fft_row_fwd(const float* __restrict__ u,
                              const float* __restrict__ cs) {
    __shared__ float2 sm[4][2][320];
    __shared__ float2 sTw[320];
    int tid = threadIdx.x;
    sTw[tid] = g_tw[tid];
    int g = tid / 80, t = tid % 80;
    int rowIdx = blockIdx.x * 4 + g;
    int r = rowIdx % HH, nc = rowIdx / HH;
    int n = nc / NCOIL;
    const float2* up = (const float2*)u + (n * HH + r) * WW;
    const float2* cp = (const float2*)cs + (nc * HH + r) * WW;
    float2* X = &sm[g][0][0];
    float2* Y = &sm[g][1][0];
    for (int x = t; x < 320; x += 80) {
        float2 q = cmulf(up[x], cp[x]);
        float sgn = ((r + x) & 1) ? -1.f : 1.f;
        X[x] = make_float2(sgn * q.x, sgn * q.y);
    }
    __syncthreads();
    fft320<-1>(X, Y, sTw, t);
    float2* dst = g_work + nc * (HH * WW) + r * WW;
    const float sc = 1.f / 320.f;
    for (int x = t; x < 320; x += 80)
        dst[x] = make_float2(X[x].x * sc, X[x].y * sc);
}

__global__ void k_fft_col_fwd(const float* __restrict__ fdat,
                              const float* __restrict__ mask) {
    __shared__ float2 sm[4][2][320];
    __shared__ float2 sTw[320];
    int tid = threadIdx.x;
    sTw[tid] = g_tw[tid];
    int blk = blockIdx.x;
    int nc = blk / 80, cb = (blk % 80) * 4;
    int n = nc / NCOIL;
    float2* base = g_work + nc * (HH * WW);
    for (int i = tid; i < 1280; i += 320) {
        int row = i >> 2, cc = i & 3;
        sm[cc][0][row] = base[row * WW + cb + cc];
    }
    __syncthreads();
    int g = tid / 80, t = tid % 80;
    fft320<-1>(&sm[g][0][0], &sm[g][1][0], sTw, t);
    const float2* f2 = (const float2*)fdat + nc * (HH * WW);
    for (int i = tid; i < 1280; i += 320) {
        int row = i >> 2, cc = i & 3;
        int col = cb + cc;
        float m = mask[n * (HH * WW) + row * WW + col];
        float2 fv = f2[row * WW + col];
        float sgn = ((row + col) & 1) ? -1.f : 1.f;
        float2 q = sm[cc][0][row];
        base[row * WW + col] =
            make_float2(m * (q.x - sgn * fv.x), m * (q.y - sgn * fv.y));
    }
}

__global__ void k_fft_row_inv() {
    __shared__ float2 sm[4][2][320];
    __shared__ float2 sTw[320];
    int tid = threadIdx.x;
    sTw[tid] = g_tw[tid];
    int g = tid / 80, t = tid % 80;
    int rowIdx = blockIdx.x * 4 + g;
    int r = rowIdx % HH, nc = rowIdx / HH;
    float2* rowp = g_work + nc * (HH * WW) + r * WW;
    float2* X = &sm[g][0][0];
    float2* Y = &sm[g][1][0];
    for (int x = t; x < 320; x += 80) X[x] = rowp[x];
    __syncthreads();
    fft320<1>(X, Y, sTw, t);
    const float sc = 1.f / 320.f;
    for (int x = t; x < 320; x += 80)
        rowp[x] = make_float2(X[x].x * sc, X[x].y * sc);
}

__global__ void k_fft_col_inv(const float* __restrict__ cs) {
    __shared__ float2 sm[4][2][320];
    __shared__ float2 sTw[320];
    int tid = threadIdx.x;
    sTw[tid] = g_tw[tid];
    int blk = blockIdx.x;
    int nc = blk / 80, cb = (blk % 80) * 4;
    float2* base = g_work + nc * (HH * WW);
    for (int i = tid; i < 1280; i += 320) {
        int row = i >> 2, cc = i & 3;
        sm[cc][0][row] = base[row * WW + cb + cc];
    }
    __syncthreads();
    int g = tid / 80, t = tid % 80;
    fft320<1>(&sm[g][0][0], &sm[g][1][0], sTw, t);
    const float2* c2 = (const float2*)cs + nc * (HH * WW);
    for (int i = tid; i < 1280; i += 320) {
        int row = i >> 2, cc = i & 3;
        int col = cb + cc;
        float2 v = sm[cc][0][row];
        float2 cv = c2[row * WW + col];
        float sgn = ((row + col) & 1) ? -1.f : 1.f;
        float2 o;
        o.x = sgn * (v.x * cv.x + v.y * cv.y);
        o.y = sgn * (v.y * cv.x - v.x * cv.y);
        base[row * WW + col] = o;
    }
}

// ----------------- adjoint conv partials (feature-paired) ------------------
// grid (5, 20, NB*4): tile 16 rows x 64 cols, chunk = 4 feature-PAIRS.
// Weights {re-pair, im-pair} as ulonglong2 -> one LDS.128 per tap.
#define FST 77
__global__ __launch_bounds__(128) void k_adj(const float* __restrict__ ck) {
    __shared__ unsigned long long sT[26 * FST];      // 16KB
    __shared__ ulonglong2 sK[121];                   // {(wreA,wreB),(wimA,wimB)}
    int zz = blockIdx.z, n = zz >> 2, chunk = zz & 3;
    int y0 = blockIdx.y * 16, x0 = blockIdx.x * 64;
    int tid = threadIdx.x;
    int ty = tid & 15, txg = (tid >> 4) << 3;   // 16 rows x (8 groups * 8 cols)
    unsigned long long accre[8], accim[8];
#pragma unroll
    for (int j = 0; j < 8; j++) { accre[j] = 0ull; accim[j] = 0ull; }
    const float2* ck2 = (const float2*)ck;
#pragma unroll 1
    for (int p = 0; p < 4; p++) {
        int fA = (chunk * 4 + p) * 2, fB = fA + 1;
        __syncthreads();
        const float* baseA = &g_fuk[(n * NF + fA) * HP * HP];
        const float* baseB = &g_fuk[(n * NF + fB) * HP * HP];
        for (int i = tid; i < 26 * FST; i += 128) {
            int ly = i / FST, lx = i % FST;
            float vA = 0.f, vB = 0.f;
            if (lx < 74) {
                int off = (y0 + 6 + ly) * HP + (x0 + 6 + lx);
                vA = baseA[off];
                vB = baseB[off];
            }
            sT[i] = pack2(vA, vB);
        }
        if (tid < 121) {
            float2 wA = ck2[fA * 121 + 120 - tid];   // reversed kernel
            float2 wB = ck2[fB * 121 + 120 - tid];
            sK[tid] = make_ulonglong2(pack2(wA.x, wB.x), pack2(wA.y, wB.y));
        }
        __syncthreads();
#pragma unroll 1
        for (int ky = 0; ky < 11; ky++) {
            unsigned long long v[18];
            const unsigned long long* rowp = &sT[(ty + ky) * FST + txg];
#pragma unroll
            for (int q = 0; q < 18; q++) v[q] = rowp[q];
#pragma unroll
            for (int kx = 0; kx < 11; kx++) {
                ulonglong2 wv = sK[ky * 11 + kx];
#pragma unroll
                for (int j = 0; j < 8; j++) {
                    fma2(accre[j], v[kx + j], wv.x);
                    fma2(accim[j], v[kx + j], wv.y);
                }
            }
        }
    }
    int y = y0 + ty;
    float2* dst = &g_adj[((chunk * NB + n) * HH + y) * WW + x0 + txg];
#pragma unroll
    for (int j = 0; j < 8; j++) {
        float a, b, c, d;
        unpack2(accre[j], a, b);
        unpack2(accim[j], c, d);
        dst[j] = make_float2(a + b, c + d);
    }
}

// ------------- final combine: u - Ru - Du  (memory-light) ------------------
__global__ void k_combine(const float* __restrict__ u,
                          const float* __restrict__ lamb,
                          float2* __restrict__ out) {
    int idx = blockIdx.x * blockDim.x + threadIdx.x;
    if (idx >= NB * HH * WW) return;
    int pix = idx % (HH * WW), n = idx / (HH * WW);
    float lam = lamb[0];
    float2 ru = make_float2(0.f, 0.f);
#pragma unroll
    for (int c = 0; c < 4; c++) {
        float2 v = g_adj[(c * NB + n) * (HH * WW) + pix];
        ru.x += v.x; ru.y += v.y;
    }
    float2 du = make_float2(0.f, 0.f);
#pragma unroll 1
    for (int c = 0; c < NCOIL; c++) {
        float2 v = g_work[(n * NCOIL + c) * (HH * WW) + pix];
        du.x += v.x; du.y += v.y;
    }
    float2 uu = ((const float2*)u)[idx];
    float2 o;
    o.x = uu.x - ru.x * (1.f / 32.f) - lam * du.x;
    o.y = uu.y - ru.y * (1.f / 32.f) - lam * du.y;
    out[idx] = o;
}

// ---------------------------------------------------------------------------
extern "C" void kernel_launch(void* const* d_in, const int* in_sizes, int n_in,
                              void* d_out, int out_size) {
    const float* u_t   = (const float*)d_in[0];
    const float* fdat  = (const float*)d_in[1];
    const float* cs    = (const float*)d_in[2];
    const float* mask  = (const float*)d_in[3];
    const float* ck    = (const float*)d_in[4];
    const float* w     = (const float*)d_in[5];
    const float* mu    = (const float*)d_in[6];
    const float* sigma = (const float*)d_in[7];
    const float* lamb  = (const float*)d_in[8];
    float2* out = (float2*)d_out;

    k_tw<<<1, 320>>>();
    k_lut<<<NF, 256>>>(w, mu, sigma);
    k_pad<<<(NB * HP * HP + 255) / 256, 256>>>(u_t);
    k_conv<<<dim3(6, 11, NB * 16), 256>>>(ck);

    int nrows = NB * NCOIL * HH;          // 19200
    k_fft_row_fwd<<<nrows / 4, 320>>>(u_t, cs);
    k_fft_col_fwd<<<NB * NCOIL * 80, 320>>>(fdat, mask);
    k_fft_row_inv<<<nrows / 4, 320>>>();
    k_fft_col_inv<<<NB * NCOIL * 80, 320>>>(cs);

    k_adj<<<dim3(5, 20, NB * 4), 128>>>(ck);
    k_combine<<<(NB * HH * WW + 255) / 256, 256>>>(u_t, lamb, out);
}